// round 17
// baseline (speedup 1.0000x reference)
#include <cuda_runtime.h>
#include <cuda_fp16.h>
#include <cstdint>

// HyperspectralAttention collapses (per-head dim == 1 => softmax == 1) to
//   out = W_proj @ ( illu * ( (0.6*W_v_spec + 0.4*W_v_spat) @ x ) )
// Two 64 x 262144 x 64 GEMMs on mma.sync, all operands single fp16
// (rel_err ~4e-4 < 1e-3 gate).
//
// R17: MAX-MLP discriminating experiment. Both X and illu stream via
// cp.async into per-warp smem (conflict-free stride-20 rows), pipeline
// 2 tiles deep, one commit group per tile. No registers / SB slots tied
// to gmem loads -> outstanding bytes no longer self-limited. GEMM1 gathers
// X frags via 32 conflict-free scalar LDS (29cyc) + pack. Wp register-
// resident; Wm ldsm'd in GEMM1. 320 thr, 1 CTA/SM, smem 221KB.

#define TPB 320
#define NWARPS 10
#define NWT 16384            // 16-px warp tiles

// smem: W 16KB + per-warp block [XB0,XB1,IB0,IB1] x 5120B
#define SM_WM   0u
#define SM_WP   8192u
#define SM_BUF  16384u
#define BUF_SZ  5120u        // 64 rows x 20 f32
#define WBLK    (4u * BUF_SZ)
#define SM_TOTAL (16384 + NWARPS * 4 * 5120)   // 221184

__device__ __forceinline__ uint32_t smem_u32(const void* p) {
    uint32_t a;
    asm("{ .reg .u64 t; cvta.to.shared.u64 t, %1; cvt.u32.u64 %0, t; }"
        : "=r"(a) : "l"(p));
    return a;
}
__device__ __forceinline__ void cp_async16(uint32_t dst, const void* src) {
    asm volatile("cp.async.cg.shared.global [%0], [%1], 16;"
                 :: "r"(dst), "l"(src) : "memory");
}
__device__ __forceinline__ void cp_commit() {
    asm volatile("cp.async.commit_group;" ::: "memory");
}
template <int N>
__device__ __forceinline__ void cp_wait() {
    asm volatile("cp.async.wait_group %0;" :: "n"(N) : "memory");
}
__device__ __forceinline__ void ldsm4(uint32_t addr, uint32_t r[4]) {
    asm volatile("ldmatrix.sync.aligned.m8n8.x4.shared.b16 {%0,%1,%2,%3}, [%4];"
                 : "=r"(r[0]), "=r"(r[1]), "=r"(r[2]), "=r"(r[3]) : "r"(addr));
}
__device__ __forceinline__ void mma16816(float c[4], const uint32_t a[4],
                                         uint32_t b0, uint32_t b1) {
    asm volatile("mma.sync.aligned.m16n8k16.row.col.f32.f16.f16.f32 "
                 "{%0,%1,%2,%3}, {%4,%5,%6,%7}, {%8,%9}, {%0,%1,%2,%3};"
                 : "+f"(c[0]), "+f"(c[1]), "+f"(c[2]), "+f"(c[3])
                 : "r"(a[0]), "r"(a[1]), "r"(a[2]), "r"(a[3]), "r"(b0), "r"(b1));
}
__device__ __forceinline__ uint32_t packh2(float v0, float v1) {
    __half2 hp = __floats2half2_rn(v0, v1);
    return *reinterpret_cast<uint32_t*>(&hp);
}

// GEMM1 B-frag ldsm addr on W[o][c]: groups = n0k0,n0k8,n8k0,n8k8
__device__ __forceinline__ uint32_t waddrB(uint32_t sbW, int ntp, int kc, int lane) {
    const int o  = ntp * 16 + ((lane >> 4) & 1) * 8 + (lane & 7);
    const int cb = kc * 32 + ((lane >> 3) & 1) * 16;
    return sbW + (uint32_t)(o * 128) + (uint32_t)(cb ^ ((o & 7) << 4));
}
// GEMM2 A-frag ldsm addr on W[o'][o]: groups = m0k0,m8k0,m0k8,m8k8
__device__ __forceinline__ uint32_t waddrA(uint32_t sbW, int mtp, int kc, int lane) {
    const int o  = mtp * 16 + ((lane >> 3) & 1) * 8 + (lane & 7);
    const int cb = kc * 32 + ((lane >> 4) & 1) * 16;
    return sbW + (uint32_t)(o * 128) + (uint32_t)(cb ^ ((o & 7) << 4));
}

__device__ __forceinline__ size_t tile_base(int t) {
    return (size_t)(t >> 12) * 4194304 + (size_t)(t & 4095) * 16;
}

// cp.async one tile's X + illu (64 rows x 16 f32 each) into smem buffers.
// Row c occupies 20 floats (80B) -> LDS bank-conflict-free reads later.
__device__ __forceinline__ void issue_tile(const float* x, const float* illu,
                                           int t, int lane,
                                           uint32_t xbuf, uint32_t ibuf) {
    const size_t base = tile_base(t);
    const float* xb = x + base;
    const float* ib = illu + base;
    #pragma unroll
    for (int k = 0; k < 8; k++) {
        const int j = lane + k * 32, c = j >> 2, q = j & 3;
        const uint32_t off = (uint32_t)(c * 80 + q * 16);
        cp_async16(xbuf + off, xb + (size_t)c * 65536 + q * 4);
        cp_async16(ibuf + off, ib + (size_t)c * 65536 + q * 4);
    }
}

__global__ __launch_bounds__(TPB, 1) void fused_h7(
    const float* __restrict__ x, const float* __restrict__ illu,
    const float* __restrict__ wvspec, const float* __restrict__ wvspat,
    const float* __restrict__ wproj, float* __restrict__ out)
{
    extern __shared__ char smem[];
    const uint32_t sb = smem_u32(smem);
    const int tid = threadIdx.x, lane = tid & 31, w = tid >> 5;
    const int g = lane >> 2, tq = lane & 3;

    // ---- weights -> smem fp16 (once) ----
    for (int i = tid; i < 4096; i += TPB) {
        const int o = i >> 6, c = i & 63;
        const uint32_t off = (uint32_t)(o * 128) +
                             (((uint32_t)(2 * c)) ^ ((uint32_t)(o & 7) << 4));
        *(__half*)(smem + SM_WM + off) =
            __float2half_rn(0.6f * wvspec[i] + 0.4f * wvspat[i]);
        *(__half*)(smem + SM_WP + off) = __float2half_rn(wproj[i]);
    }
    __syncthreads();

    // Wp register-resident (GEMM2 A-frags)
    uint32_t wp[16][4];
    #pragma unroll
    for (int kc = 0; kc < 4; kc++)
        #pragma unroll
        for (int p = 0; p < 4; p++)
            ldsm4(waddrA(sb + SM_WP, p, kc, lane), wp[kc * 4 + p]);

    const uint32_t sbWM = sb + SM_WM;
    const uint32_t wblk = sb + SM_BUF + (uint32_t)w * WBLK;   // XB0,XB1,IB0,IB1
    const char* wblk_c = smem + SM_BUF + (size_t)w * WBLK;

    int t = blockIdx.x * NWARPS + w;
    const int stride = gridDim.x * NWARPS;
    if (t >= NWT) return;

    // ---- prologue: 2-deep prefetch (one group per tile) ----
    issue_tile(x, illu, t, lane, wblk, wblk + 2 * BUF_SZ);
    cp_commit();
    if (t + stride < NWT)
        issue_tile(x, illu, t + stride, lane,
                   wblk + BUF_SZ, wblk + 3 * BUF_SZ);
    cp_commit();

    int buf = 0;
    while (t < NWT) {
        const int tn  = t + stride;
        const int tnn = t + 2 * stride;

        cp_wait<1>();          // tile t's group complete (t+1 may fly)
        __syncwarp();          // all lanes' cp writes for t visible

        const float* XS = (const float*)(wblk_c + (size_t)buf * BUF_SZ);
        const float* IL = (const float*)(wblk_c + (size_t)(2 + buf) * BUF_SZ);

        // ---- gather X(t) frags from smem (conflict-free LDS) + pack ----
        uint32_t xh[4][4];
        #pragma unroll
        for (int kc = 0; kc < 4; kc++) {
            const int r0 = kc * 16 + 2 * tq;
            const float a0 = XS[r0 * 20 + g],       a1 = XS[(r0 + 1) * 20 + g];
            const float a2 = XS[r0 * 20 + g + 8],   a3 = XS[(r0 + 1) * 20 + g + 8];
            const float a4 = XS[(r0 + 8) * 20 + g], a5 = XS[(r0 + 9) * 20 + g];
            const float a6 = XS[(r0 + 8) * 20 + g + 8],
                        a7 = XS[(r0 + 9) * 20 + g + 8];
            xh[kc][0] = packh2(a0, a1);
            xh[kc][1] = packh2(a2, a3);
            xh[kc][2] = packh2(a4, a5);
            xh[kc][3] = packh2(a6, a7);
        }

        // ---- GEMM1: acc1[px16][o64] = X^T @ Wm^T (Wm via ldsm) ----
        float acc1[8][4];
        #pragma unroll
        for (int nt = 0; nt < 8; nt++)
            #pragma unroll
            for (int q = 0; q < 4; q++) acc1[nt][q] = 0.0f;

        #pragma unroll
        for (int kc = 0; kc < 4; kc++) {
            #pragma unroll
            for (int ntp = 0; ntp < 4; ntp++) {
                uint32_t b[4];
                ldsm4(waddrB(sbWM, ntp, kc, lane), b);
                mma16816(acc1[2 * ntp],     xh[kc], b[0], b[1]);
                mma16816(acc1[2 * ntp + 1], xh[kc], b[2], b[3]);
            }
        }

        // ---- GEMM2 (swapped): acc2[o'64][px16] = Wp @ (illu * D1) ----
        float acc2[4][2][4];
        #pragma unroll
        for (int mt = 0; mt < 4; mt++)
            #pragma unroll
            for (int nt = 0; nt < 2; nt++)
                #pragma unroll
                for (int q = 0; q < 4; q++) acc2[mt][nt][q] = 0.0f;

        #pragma unroll
        for (int kc = 0; kc < 4; kc++) {
            const int nA = 2 * kc, nB = 2 * kc + 1;
            const int o0 = nA * 8 + 2 * tq;
            const int o8 = nB * 8 + 2 * tq;
            uint32_t blo[2], bhi[2];
            blo[0] = packh2(acc1[nA][0] * IL[o0 * 20 + g],
                            acc1[nA][1] * IL[(o0 + 1) * 20 + g]);
            blo[1] = packh2(acc1[nB][0] * IL[o8 * 20 + g],
                            acc1[nB][1] * IL[(o8 + 1) * 20 + g]);
            bhi[0] = packh2(acc1[nA][2] * IL[o0 * 20 + g + 8],
                            acc1[nA][3] * IL[(o0 + 1) * 20 + g + 8]);
            bhi[1] = packh2(acc1[nB][2] * IL[o8 * 20 + g + 8],
                            acc1[nB][3] * IL[(o8 + 1) * 20 + g + 8]);
            #pragma unroll
            for (int mt = 0; mt < 4; mt++) {
                const uint32_t* aW = wp[kc * 4 + mt];
                mma16816(acc2[mt][0], aW, blo[0], blo[1]);
                mma16816(acc2[mt][1], aW, bhi[0], bhi[1]);
            }
        }
        __syncwarp();          // all lanes done reading XS/IL buffers of t

        // ---- issue tile t+2 into the buffer t just vacated ----
        if (tnn < NWT)
            issue_tile(x, illu, tnn, lane,
                       wblk + (uint32_t)buf * BUF_SZ,
                       wblk + (uint32_t)(2 + buf) * BUF_SZ);
        cp_commit();           // unconditional: exact group counting

        // ---- store: acc2 (m=o', n=px) -> float2 per lane ----
        {
            float* obp = out + tile_base(t);
            #pragma unroll
            for (int mt = 0; mt < 4; mt++)
                #pragma unroll
                for (int nt = 0; nt < 2; nt++) {
                    const int o0 = mt * 16 + g;
                    const int px = nt * 8 + 2 * tq;
                    *(float2*)(obp + (size_t)o0 * 65536 + px) =
                        make_float2(acc2[mt][nt][0], acc2[mt][nt][1]);
                    *(float2*)(obp + (size_t)(o0 + 8) * 65536 + px) =
                        make_float2(acc2[mt][nt][2], acc2[mt][nt][3]);
                }
        }
        buf ^= 1;
        t = tn;
    }
}

extern "C" void kernel_launch(void* const* d_in, const int* in_sizes, int n_in,
                              void* d_out, int out_size)
{
    const float* x      = (const float*)d_in[0];
    const float* illu   = (const float*)d_in[1];
    const float* wvspec = (const float*)d_in[4];
    const float* wvspat = (const float*)d_in[7];
    const float* wproj  = (const float*)d_in[10];
    float* out = (float*)d_out;

    int dev = 0, sms = 148;
    cudaGetDevice(&dev);
    cudaDeviceGetAttribute(&sms, cudaDevAttrMultiProcessorCount, dev);
    if (sms < 1) sms = 148;
    int grid = sms;                      // 1 CTA/SM
    if (grid * NWARPS > NWT) grid = NWT / NWARPS;

    cudaFuncSetAttribute(fused_h7, cudaFuncAttributeMaxDynamicSharedMemorySize,
                         SM_TOTAL);
    fused_h7<<<grid, TPB, SM_TOTAL>>>(x, illu, wvspec, wvspat, wproj, out);
}